// round 13
// baseline (speedup 1.0000x reference)
#include <cuda_runtime.h>
#include <cuda_fp16.h>
#include <math.h>
#include <stdint.h>

#define HDIM 512
#define BATCH 8
#define SEQL 1024
#define MTOT 8192

// half scratch: 84M halves = 168MB
__device__ __half g_scratch[(size_t)84 * 1024 * 1024];
__device__ float zbias[512] = {};   // zero bias for prep gemms

// ---------------------------------------------------------------------------
// Primitives
// ---------------------------------------------------------------------------
__device__ __forceinline__ void mma_f16(float& d0, float& d1, float& d2, float& d3,
                                        uint32_t a0, uint32_t a1, uint32_t a2, uint32_t a3,
                                        uint32_t b0, uint32_t b1)
{
    asm volatile(
        "mma.sync.aligned.m16n8k16.row.col.f32.f16.f16.f32 "
        "{%0,%1,%2,%3}, {%4,%5,%6,%7}, {%8,%9}, {%0,%1,%2,%3};"
        : "+f"(d0), "+f"(d1), "+f"(d2), "+f"(d3)
        : "r"(a0), "r"(a1), "r"(a2), "r"(a3), "r"(b0), "r"(b1));
}

__device__ __forceinline__ void ldsm4(uint32_t& r0, uint32_t& r1, uint32_t& r2, uint32_t& r3,
                                      uint32_t addr)
{
    asm volatile("ldmatrix.sync.aligned.m8n8.x4.shared.b16 {%0,%1,%2,%3}, [%4];"
                 : "=r"(r0), "=r"(r1), "=r"(r2), "=r"(r3) : "r"(addr));
}
__device__ __forceinline__ void ldsm4t(uint32_t& r0, uint32_t& r1, uint32_t& r2, uint32_t& r3,
                                       uint32_t addr)
{
    asm volatile("ldmatrix.sync.aligned.m8n8.x4.trans.shared.b16 {%0,%1,%2,%3}, [%4];"
                 : "=r"(r0), "=r"(r1), "=r"(r2), "=r"(r3) : "r"(addr));
}

__device__ __forceinline__ void cp16(uint32_t dst, const void* src) {
    asm volatile("cp.async.cg.shared.global [%0], [%1], 16;" :: "r"(dst), "l"(src));
}
__device__ __forceinline__ void cpcommit() { asm volatile("cp.async.commit_group;"); }
template<int N> __device__ __forceinline__ void cpwait() {
    asm volatile("cp.async.wait_group %0;" :: "n"(N));
}

// XOR swizzle: rows of 128B (64 halves), 16B chunk c in 0..7
__device__ __forceinline__ uint32_t swz(uint32_t r, uint32_t c) {
    return r * 128u + ((c ^ (r & 7u)) << 4);
}

__device__ __forceinline__ uint32_t packh2(float x, float y) {
    __half2 h = __floats2half2_rn(x, y);
    return *(uint32_t*)&h;
}

// ---------------------------------------------------------------------------
// fp32 -> fp16 conversion kernel
// ---------------------------------------------------------------------------
struct CvtP { const float* src[11]; __half* dst[11]; int nblk[11]; };

__global__ __launch_bounds__(256) void cvt_k(CvtP P)
{
    int b = blockIdx.x;
    int s = 0;
    while (b >= P.nblk[s]) { b -= P.nblk[s]; ++s; }
    size_t i = ((size_t)b * 256 + threadIdx.x) * 4;
    float4 v = *(const float4*)(P.src[s] + i);
    uint2 o;
    o.x = packh2(v.x, v.y);
    o.y = packh2(v.z, v.w);
    *(uint2*)(P.dst[s] + i) = o;
}

// ---------------------------------------------------------------------------
// transpose + cvt: dst[n,k] = fp16(src[k,n]) for 512x512 fp32 matrices
// ---------------------------------------------------------------------------
struct TrP { const float* src[2]; __half* dst[2]; };

__global__ void tcv_k(TrP P)
{
    __shared__ __half tile[32][33];
    const int s = blockIdx.z;
    const int x = blockIdx.x * 32, y = blockIdx.y * 32;
    const int tx = threadIdx.x, ty = threadIdx.y;
    const float* src = P.src[s];
    #pragma unroll
    for (int r = ty; r < 32; r += 8)
        tile[r][tx] = __float2half_rn(src[(size_t)(y + r) * 512 + x + tx]);
    __syncthreads();
    __half* dst = P.dst[s];
    #pragma unroll
    for (int r = ty; r < 32; r += 8)
        dst[(size_t)(x + r) * 512 + y + tx] = tile[tx][r];
}

// ---------------------------------------------------------------------------
// generic bias combine, warp-per-row:
//   bout[row] = badd[row] + sum_j Wh[row,j] * (j<split ? b0[j] : b1[j-split])
// block = 512 (16 warps), grid = rows/16
// ---------------------------------------------------------------------------
__global__ __launch_bounds__(512) void bias2_k(
    const __half* __restrict__ Wh, int ldw, int K,
    const float* __restrict__ b0, const float* __restrict__ b1, int split,
    const float* __restrict__ badd, float* __restrict__ bout)
{
    const int row = blockIdx.x * 16 + (threadIdx.x >> 5);
    const int lane = threadIdx.x & 31;
    float s = 0.f;
    for (int j = lane; j < K; j += 32) {
        const float b = (j < split) ? b0[j] : b1[j - split];
        s += __half2float(Wh[(size_t)row * ldw + j]) * b;
    }
    #pragma unroll
    for (int o = 16; o; o >>= 1) s += __shfl_xor_sync(0xffffffffu, s, o);
    if (lane == 0) bout[row] = s + badd[row];
}

// ---------------------------------------------------------------------------
// FP16 GEMM (NT): C = A @ W^T + bias, times per-seg osc. Pure cp.async A path.
// W row stride ldw (independent of K extent). CTA 128x128, BK=64, 256 thr.
// 3-stage cp.async pipeline (96KB smem), single sync/iter, XOR swizzle.
// ---------------------------------------------------------------------------
struct GemmP {
    const __half* A1[6];
    const __half* W[6]; const float* Bi[6];
    __half* Ch[6]; float* Cf;
    float osc[6];
    int lda, ldc, K, ldw;
};

template<bool OUTF32>
__global__ __launch_bounds__(256, 2) void gemm_k(GemmP P)
{
    extern __shared__ char sm[];
    const uint32_t smb = (uint32_t)__cvta_generic_to_shared(sm);

    const int bm  = blockIdx.y * 128;
    const int bnG = blockIdx.x * 128;
    const int seg = bnG >> 9;
    const int bn  = bnG & 511;
    const __half* A1 = P.A1[seg];
    const __half* W  = P.W[seg];
    const float*  BI = P.Bi[seg];
    const float  osc = P.osc[seg];

    const int tid  = threadIdx.x;
    const int warp = tid >> 5;
    const int lane = tid & 31;
    const int g = lane >> 2;
    const int t = lane & 3;
    const int wm = warp >> 2;
    const int wn = warp & 3;
    const int lr = lane & 15;
    const int lh = lane >> 4;

    const int sr = tid >> 1;
    const int sc = (tid & 1) * 4;

    const uint32_t lrow128 = (uint32_t)lr * 128u;
    uint32_t x4[4];
    #pragma unroll
    for (int kb = 0; kb < 4; kb++)
        x4[kb] = (uint32_t)(((kb * 2 + lh) ^ (lr & 7)) << 4);

    const int NK = P.K >> 6;
    float acc[4][4][4] = {};

    auto stage = [&](int i) {
        const uint32_t da = smb + (uint32_t)(i % 3) * 32768u;
        const __half* sa = A1 + (size_t)(bm + sr) * P.lda + i * 64 + sc * 8;
        const __half* sw = W  + (size_t)(bn + sr) * P.ldw + i * 64 + sc * 8;
        #pragma unroll
        for (int c = 0; c < 4; c++) {
            cp16(da + swz(sr, sc + c), sa + c * 8);
            cp16(da + 16384u + swz(sr, sc + c), sw + c * 8);
        }
        cpcommit();
    };

    stage(0);
    if (NK > 1) stage(1);

    for (int i = 0; i < NK; i++) {
        if (i + 1 < NK) cpwait<1>(); else cpwait<0>();
        __syncthreads();

        const uint32_t Ab = smb + (uint32_t)(i % 3) * 32768u;
        const uint32_t Wb = Ab + 16384u;

        #pragma unroll
        for (int kb = 0; kb < 4; kb++) {
            uint32_t bw[2][4];
            #pragma unroll
            for (int np = 0; np < 2; np++)
                ldsm4(bw[np][0], bw[np][1], bw[np][2], bw[np][3],
                      Wb + (uint32_t)(wn * 32 + np * 16) * 128u + lrow128 + x4[kb]);
            #pragma unroll
            for (int mt = 0; mt < 4; mt++) {
                uint32_t a0, a1, a2, a3;
                ldsm4(a0, a1, a2, a3,
                      Ab + (uint32_t)(wm * 64 + mt * 16) * 128u + lrow128 + x4[kb]);
                #pragma unroll
                for (int nt = 0; nt < 4; nt++) {
                    const int np = nt >> 1, hi = nt & 1;
                    mma_f16(acc[mt][nt][0], acc[mt][nt][1], acc[mt][nt][2], acc[mt][nt][3],
                            a0, a1, a2, a3,
                            bw[np][hi ? 1 : 0], bw[np][hi ? 3 : 2]);
                }
            }
        }

        if (i + 2 < NK) stage(i + 2);
    }

    #pragma unroll
    for (int mt = 0; mt < 4; mt++) {
        const int r = bm + wm * 64 + mt * 16 + g;
        #pragma unroll
        for (int nt = 0; nt < 4; nt++) {
            const int cl = bn + wn * 32 + nt * 8 + 2 * t;
            const float bx = BI[cl], by = BI[cl + 1];
            if (OUTF32) {
                float* Cf = P.Cf;
                *(float2*)(Cf + (size_t)r * P.ldc + cl) =
                    make_float2((acc[mt][nt][0] + bx) * osc, (acc[mt][nt][1] + by) * osc);
                *(float2*)(Cf + (size_t)(r + 8) * P.ldc + cl) =
                    make_float2((acc[mt][nt][2] + bx) * osc, (acc[mt][nt][3] + by) * osc);
            } else {
                __half* Ch = P.Ch[seg];
                *(uint32_t*)(Ch + (size_t)r * P.ldc + cl) =
                    packh2((acc[mt][nt][0] + bx) * osc, (acc[mt][nt][1] + by) * osc);
                *(uint32_t*)(Ch + (size_t)(r + 8) * P.ldc + cl) =
                    packh2((acc[mt][nt][2] + bx) * osc, (acc[mt][nt][3] + by) * osc);
            }
        }
    }
}

// ---------------------------------------------------------------------------
// FP16 flash attention (R12 winner — unchanged). DUAL: two KV streams vs one Q.
// ---------------------------------------------------------------------------
struct FlashP {
    const __half *Qp[4], *Kp[4], *Vp[4], *Kp2[4], *Vp2[4]; __half* Op[4];
    int sq, skv, so, cmask, cshift;
};

#define OS_STRIDE 68

template<bool DUAL>
__global__ __launch_bounds__(256, 2) void flash_k(FlashP P)
{
    extern __shared__ char fsm[];
    const uint32_t smb = (uint32_t)__cvta_generic_to_shared(fsm);

    const int z = blockIdx.z;
    const int c = z & P.cmask;
    const int b = z >> P.cshift;
    const int q0 = blockIdx.x * 128;
    const int h  = blockIdx.y;

    const int tid = threadIdx.x;
    const int w = tid >> 5;
    const int lane = tid & 31;
    const int g = lane >> 2;
    const int t = lane & 3;
    const int lr = lane & 15;
    const int lh = lane >> 4;

    const __half* Qb  = P.Qp[c] + (size_t)b * SEQL * P.sq  + (size_t)h * 64;
    const __half* Kb  = P.Kp[c] + (size_t)b * SEQL * P.skv + (size_t)h * 64;
    const __half* Vb  = P.Vp[c] + (size_t)b * SEQL * P.skv + (size_t)h * 64;
    const __half* Kb2 = DUAL ? P.Kp2[c] + (size_t)b * SEQL * P.skv + (size_t)h * 64 : nullptr;
    const __half* Vb2 = DUAL ? P.Vp2[c] + (size_t)b * SEQL * P.skv + (size_t)h * 64 : nullptr;
    __half*       Ob  = P.Op[c] + (size_t)b * SEQL * P.so  + (size_t)h * 64;

    const uint32_t lrow128 = (uint32_t)lr * 128u;
    uint32_t x4[4];
    #pragma unroll
    for (int kb = 0; kb < 4; kb++)
        x4[kb] = (uint32_t)(((kb * 2 + lh) ^ (lr & 7)) << 4);

    {
        const int sr = tid >> 1;
        const int sc = (tid & 1) * 4;
        const __half* src = Qb + (size_t)(q0 + sr) * P.sq + sc * 8;
        #pragma unroll
        for (int cc = 0; cc < 4; cc++)
            cp16(smb + swz(sr, sc + cc), src + cc * 8);
        cpcommit();
    }

    const int kr = tid >> 2;
    const int kc = (tid & 3) * 2;
    auto stageKV = [&](int tile) {
        const int s = tile % 3;
        const int kt = (DUAL ? (tile & 15) : tile) * 64;
        const __half* pk0 = (DUAL && (tile >> 4)) ? Kb2 : Kb;
        const __half* pv0 = (DUAL && (tile >> 4)) ? Vb2 : Vb;
        const __half* pk = pk0 + (size_t)(kt + kr) * P.skv + kc * 8;
        const __half* pv = pv0 + (size_t)(kt + kr) * P.skv + kc * 8;
        const uint32_t kbase = smb + 16384u + (uint32_t)s * 8192u;
        const uint32_t vbase = smb + 40960u + (uint32_t)s * 8192u;
        cp16(kbase + swz(kr, kc),     pk);
        cp16(kbase + swz(kr, kc + 1), pk + 8);
        cp16(vbase + swz(kr, kc),     pv);
        cp16(vbase + swz(kr, kc + 1), pv + 8);
        cpcommit();
    };

    stageKV(0);
    stageKV(1);
    cpwait<1>();
    __syncthreads();

    uint32_t qa[4][4];
    #pragma unroll
    for (int kb = 0; kb < 4; kb++)
        ldsm4(qa[kb][0], qa[kb][1], qa[kb][2], qa[kb][3],
              smb + (uint32_t)(w * 2048) + lrow128 + x4[kb]);

    float oacc[8][4] = {};
    float mi0 = -INFINITY, mi1 = -INFINITY;
    float li0 = 0.f, li1 = 0.f;

    const uint32_t ONES = 0x3C003C00u;
    float* Os = (float*)(fsm + 65536);
    const int rr = 16 * w + g;

    const int NT = DUAL ? 32 : 16;
    for (int it = 0; it < NT; it++) {
        const int s = it % 3;
        const uint32_t Kbase = smb + 16384u + (uint32_t)s * 8192u + lrow128;
        const uint32_t Vbase = smb + 40960u + (uint32_t)s * 8192u + lrow128;

        float sacc[8][4] = {};
        #pragma unroll
        for (int kb = 0; kb < 4; kb++) {
            #pragma unroll
            for (int np = 0; np < 4; np++) {
                uint32_t k0, k1, k2, k3;
                ldsm4(k0, k1, k2, k3, Kbase + (uint32_t)(np * 2048) + x4[kb]);
                mma_f16(sacc[2*np][0], sacc[2*np][1], sacc[2*np][2], sacc[2*np][3],
                        qa[kb][0], qa[kb][1], qa[kb][2], qa[kb][3], k0, k2);
                mma_f16(sacc[2*np+1][0], sacc[2*np+1][1], sacc[2*np+1][2], sacc[2*np+1][3],
                        qa[kb][0], qa[kb][1], qa[kb][2], qa[kb][3], k1, k3);
            }
        }

        uint32_t pa[4][4];
        {
            float mx0 = -INFINITY, mx1 = -INFINITY;
            #pragma unroll
            for (int nt = 0; nt < 8; nt++) {
                mx0 = fmaxf(mx0, fmaxf(sacc[nt][0], sacc[nt][1]));
                mx1 = fmaxf(mx1, fmaxf(sacc[nt][2], sacc[nt][3]));
            }
            mx0 = fmaxf(mx0, __shfl_xor_sync(0xffffffffu, mx0, 1, 4));
            mx0 = fmaxf(mx0, __shfl_xor_sync(0xffffffffu, mx0, 2, 4));
            mx1 = fmaxf(mx1, __shfl_xor_sync(0xffffffffu, mx1, 1, 4));
            mx1 = fmaxf(mx1, __shfl_xor_sync(0xffffffffu, mx1, 2, 4));
            const float mn0 = fmaxf(mi0, mx0);
            const float mn1 = fmaxf(mi1, mx1);
            const float c0 = exp2f(mi0 - mn0);
            const float c1 = exp2f(mi1 - mn1);
            mi0 = mn0; mi1 = mn1;

            float ls[4] = {0.f, 0.f, 0.f, 0.f};
            #pragma unroll
            for (int kb = 0; kb < 4; kb++) {
                __half2 e0 = h2exp2(__floats2half2_rn(sacc[2*kb][0]   - mn0, sacc[2*kb][1]   - mn0));
                __half2 e1 = h2exp2(__floats2half2_rn(sacc[2*kb][2]   - mn1, sacc[2*kb][3]   - mn1));
                __half2 e2 = h2exp2(__floats2half2_rn(sacc[2*kb+1][0] - mn0, sacc[2*kb+1][1] - mn0));
                __half2 e3 = h2exp2(__floats2half2_rn(sacc[2*kb+1][2] - mn1, sacc[2*kb+1][3] - mn1));
                pa[kb][0] = *(uint32_t*)&e0;
                pa[kb][1] = *(uint32_t*)&e1;
                pa[kb][2] = *(uint32_t*)&e2;
                pa[kb][3] = *(uint32_t*)&e3;
                mma_f16(ls[0], ls[1], ls[2], ls[3],
                        pa[kb][0], pa[kb][1], pa[kb][2], pa[kb][3], ONES, ONES);
            }
            li0 = li0 * c0 + ls[0];
            li1 = li1 * c1 + ls[2];

            const bool skip = __all_sync(0xffffffffu, (c0 == 1.0f) & (c1 == 1.0f));
            if (!skip) {
                #pragma unroll
                for (int nt = 0; nt < 8; nt++) {
                    oacc[nt][0] *= c0; oacc[nt][1] *= c0;
                    oacc[nt][2] *= c1; oacc[nt][3] *= c1;
                }
            }
        }

        #pragma unroll
        for (int kb = 0; kb < 4; kb++) {
            #pragma unroll
            for (int np = 0; np < 4; np++) {
                uint32_t v0, v1, v2, v3;
                ldsm4t(v0, v1, v2, v3, Vbase + (uint32_t)(kb * 2048) + x4[np]);
                mma_f16(oacc[2*np][0], oacc[2*np][1], oacc[2*np][2], oacc[2*np][3],
                        pa[kb][0], pa[kb][1], pa[kb][2], pa[kb][3], v0, v1);
                mma_f16(oacc[2*np+1][0], oacc[2*np+1][1], oacc[2*np+1][2], oacc[2*np+1][3],
                        pa[kb][0], pa[kb][1], pa[kb][2], pa[kb][3], v2, v3);
            }
        }

        // DUAL phase boundary: stash normalized phase-A output, reset stats
        if (DUAL && it == 15) {
            const float s0 = 0.5f / li0;
            const float s1 = 0.5f / li1;
            #pragma unroll
            for (int nt = 0; nt < 8; nt++) {
                const int col = nt * 8 + 2 * t;
                Os[rr * OS_STRIDE + col]           = oacc[nt][0] * s0;
                Os[rr * OS_STRIDE + col + 1]       = oacc[nt][1] * s0;
                Os[(rr + 8) * OS_STRIDE + col]     = oacc[nt][2] * s1;
                Os[(rr + 8) * OS_STRIDE + col + 1] = oacc[nt][3] * s1;
                oacc[nt][0] = oacc[nt][1] = oacc[nt][2] = oacc[nt][3] = 0.f;
            }
            mi0 = mi1 = -INFINITY;
            li0 = li1 = 0.f;
        }

        if (it + 1 < NT) {
            if (it + 2 < NT) { stageKV(it + 2); cpwait<1>(); }
            else             { cpwait<0>(); }
            __syncthreads();
        }
    }

    if (DUAL) {
        const float inv0 = 0.5f / li0;
        const float inv1 = 0.5f / li1;
        const int r0 = q0 + rr;
        #pragma unroll
        for (int nt = 0; nt < 8; nt++) {
            const int col = nt * 8 + 2 * t;
            float o00 = Os[rr * OS_STRIDE + col]           + oacc[nt][0] * inv0;
            float o01 = Os[rr * OS_STRIDE + col + 1]       + oacc[nt][1] * inv0;
            float o10 = Os[(rr + 8) * OS_STRIDE + col]     + oacc[nt][2] * inv1;
            float o11 = Os[(rr + 8) * OS_STRIDE + col + 1] + oacc[nt][3] * inv1;
            *(uint32_t*)(Ob + (size_t)r0 * P.so + col)       = packh2(o00, o01);
            *(uint32_t*)(Ob + (size_t)(r0 + 8) * P.so + col) = packh2(o10, o11);
        }
    } else {
        const float inv0 = 1.0f / li0;
        const float inv1 = 1.0f / li1;
        const int r0 = q0 + rr;
        #pragma unroll
        for (int nt = 0; nt < 8; nt++) {
            const int col = nt * 8 + 2 * t;
            *(uint32_t*)(Ob + (size_t)r0 * P.so + col) =
                packh2(oacc[nt][0] * inv0, oacc[nt][1] * inv0);
            *(uint32_t*)(Ob + (size_t)(r0 + 8) * P.so + col) =
                packh2(oacc[nt][2] * inv1, oacc[nt][3] * inv1);
        }
    }
}

// ---------------------------------------------------------------------------
extern "C" void kernel_launch(void* const* d_in, const int* in_sizes, int n_in,
                              void* d_out, int out_size)
{
    (void)in_sizes; (void)n_in; (void)out_size;

    const float* hs        = (const float*)d_in[0];
    const float* txt       = (const float*)d_in[1];
    const float* w_q_img   = (const float*)d_in[2];
    const float* b_q_img   = (const float*)d_in[3];
    const float* w_k_img   = (const float*)d_in[4];
    const float* b_k_img   = (const float*)d_in[5];
    const float* w_v_img   = (const float*)d_in[6];
    const float* b_v_img   = (const float*)d_in[7];
    const float* w_q_txt   = (const float*)d_in[8];
    const float* b_q_txt   = (const float*)d_in[9];
    const float* w_k_txt   = (const float*)d_in[10];
    const float* b_k_txt   = (const float*)d_in[11];
    const float* w_v_txt   = (const float*)d_in[12];
    const float* b_v_txt   = (const float*)d_in[13];
    const float* w_out_img = (const float*)d_in[14];
    const float* b_out_img = (const float*)d_in[15];
    const float* w_out_txt = (const float*)d_in[16];
    const float* b_out_txt = (const float*)d_in[17];
    const float* w_cat     = (const float*)d_in[18];
    const float* b_cat     = (const float*)d_in[19];
    const float* in_proj_w = (const float*)d_in[20];
    const float* in_proj_b = (const float*)d_in[21];
    const float* out_proj_w= (const float*)d_in[22];
    const float* out_proj_b= (const float*)d_in[23];
    float* out = (float*)d_out;

    constexpr size_t U  = (size_t)MTOT * HDIM;      // 4.19M halves
    constexpr size_t QW = (size_t)512 * 512;
    const float qsc = 0.125f * 1.4426950408889634f; // (1/sqrt(64))*log2(e)

    __half* S;
    cudaGetSymbolAddress((void**)&S, g_scratch);
    float* zb;
    cudaGetSymbolAddress((void**)&zb, zbias);

    __half* HSh    = S;
    __half* TXTh   = S + U;
    __half* QKV0h  = S + 2 * U;
    __half* QKV1h  = S + 5 * U;
    __half* OUTC   = S + 8 * U;               // [8192 x 1024] half
    // prep area at S + 10U:
    __half* WOIT   = S + 10 * U;              // [512 x 512]
    __half* WOTT   = WOIT + QW;               // [512 x 512]
    __half* WCOMBT = WOTT + QW;               // [1024 x 512] (WCOMB^T)
    __half* W2     = WCOMBT + 2 * QW;         // [1536 x 1024]
    float*  BCOMB  = (float*)(W2 + 6 * QW);   // [512]
    float*  BCOMB2 = BCOMB + 512;             // [1536]
    __half* QKV2h  = S + 12 * U;
    __half* CTXh   = S + 15 * U;
    __half* WB     = S + 16 * U;
    __half* whqi = WB;           __half* whki = WB + QW;     __half* whvi = WB + 2 * QW;
    __half* whqt = WB + 3 * QW;  __half* whkt = WB + 4 * QW; __half* whvt = WB + 5 * QW;
    __half* whop = WB + 6 * QW;
    __half* whcat = WB + 7 * QW;            // 512*1024
    __half* whinp = whcat + 512 * 1024;     // 1536*512

    const int GSM   = 98304;
    const int FSM_S = 65536;
    const int FSM_D = 65536 + 128 * OS_STRIDE * 4;
    cudaFuncSetAttribute(gemm_k<false>,  cudaFuncAttributeMaxDynamicSharedMemorySize, GSM);
    cudaFuncSetAttribute(gemm_k<true>,   cudaFuncAttributeMaxDynamicSharedMemorySize, GSM);
    cudaFuncSetAttribute(flash_k<false>, cudaFuncAttributeMaxDynamicSharedMemorySize, FSM_S);
    cudaFuncSetAttribute(flash_k<true>,  cudaFuncAttributeMaxDynamicSharedMemorySize, FSM_D);

    // 0) fp32 -> fp16 conversions
    {
        CvtP p;
        const float* srcs[11] = {hs, txt, w_q_img, w_k_img, w_v_img, w_q_txt, w_k_txt,
                                 w_v_txt, out_proj_w, w_cat, in_proj_w};
        __half* dsts[11] = {HSh, TXTh, whqi, whki, whvi, whqt, whkt,
                            whvt, whop, whcat, whinp};
        int ns[11] = {(int)U, (int)U, (int)QW, (int)QW, (int)QW, (int)QW, (int)QW,
                      (int)QW, (int)QW, 512*1024, 1536*512};
        int tot = 0;
        for (int i = 0; i < 11; i++) { p.src[i]=srcs[i]; p.dst[i]=dsts[i]; p.nblk[i]=ns[i]/1024; tot+=ns[i]/1024; }
        cvt_k<<<tot, 256>>>(p);
    }

    // 0b) transpose+cvt w_out_img / w_out_txt
    {
        TrP p;
        p.src[0] = w_out_img; p.dst[0] = WOIT;
        p.src[1] = w_out_txt; p.dst[1] = WOTT;
        tcv_k<<<dim3(16, 16, 2), dim3(32, 8)>>>(p);
    }

    // 0c) WCOMBT[j,n] = sum_m WOIT[j,m]*wcat[n,m] (rows 0..511);
    //     rows 512..1023 use WOTT and wcat_R.
    {
        GemmP p = {};
        p.A1[0] = WOIT; p.W[0] = whcat; p.Bi[0] = zb;
        p.Ch[0] = WCOMBT; p.osc[0] = 1.f;
        p.lda = 512; p.ldc = 512; p.K = 512; p.ldw = 1024;
        gemm_k<false><<<dim3(4, 4), dim3(256), GSM>>>(p);
        p.A1[0] = WOTT; p.W[0] = whcat + 512;
        p.Ch[0] = WCOMBT + 512 * 512;
        gemm_k<false><<<dim3(4, 4), dim3(256), GSM>>>(p);
    }

    // 0d) BCOMB[n] = b_cat[n] + sum_j whcat[n,j]*([boi;bot])[j]
    bias2_k<<<32, 512>>>(whcat, 1024, 1024, b_out_img, b_out_txt, 512, b_cat, BCOMB);

    // 0e) W2[o,j] = sum_k whinp[o,k]*WCOMBT[j,k]  -> [1536 x 1024]
    {
        GemmP p = {};
        p.A1[0] = p.A1[1] = whinp;
        p.W[0] = WCOMBT; p.W[1] = WCOMBT + 512 * 512;
        p.Bi[0] = p.Bi[1] = zb;
        p.Ch[0] = W2; p.Ch[1] = W2 + 512;
        p.osc[0] = p.osc[1] = 1.f;
        p.lda = 512; p.ldc = 1024; p.K = 512; p.ldw = 512;
        gemm_k<false><<<dim3(8, 12), dim3(256), GSM>>>(p);
    }

    // 0f) BCOMB2[o] = in_proj_b[o] + sum_k whinp[o,k]*BCOMB[k]
    bias2_k<<<96, 512>>>(whinp, 512, 512, BCOMB, BCOMB, 512, in_proj_b, BCOMB2);

    const dim3 blk(256);

    // 1) BOTH QKV projections in one launch (6 half segments), Q pre-scaled
    {
        GemmP p = {};
        p.A1[0] = p.A1[1] = p.A1[2] = HSh;
        p.A1[3] = p.A1[4] = p.A1[5] = TXTh;
        p.W[0] = whqi; p.W[1] = whki; p.W[2] = whvi;
        p.W[3] = whqt; p.W[4] = whkt; p.W[5] = whvt;
        p.Bi[0] = b_q_img; p.Bi[1] = b_k_img; p.Bi[2] = b_v_img;
        p.Bi[3] = b_q_txt; p.Bi[4] = b_k_txt; p.Bi[5] = b_v_txt;
        p.Ch[0] = QKV0h; p.Ch[1] = QKV0h + 512; p.Ch[2] = QKV0h + 1024;
        p.Ch[3] = QKV1h; p.Ch[4] = QKV1h + 512; p.Ch[5] = QKV1h + 1024;
        p.osc[0] = qsc; p.osc[1] = 1.f; p.osc[2] = 1.f;
        p.osc[3] = qsc; p.osc[4] = 1.f; p.osc[5] = 1.f;
        p.lda = HDIM; p.ldc = 3 * HDIM; p.K = HDIM; p.ldw = HDIM;
        gemm_k<false><<<dim3(24, 64), blk, GSM>>>(p);
    }

    // 2) dual-KV fused attentions
    {
        FlashP p;
        p.Qp[0] = QKV0h; p.Kp[0] = QKV0h + 512; p.Vp[0] = QKV0h + 1024;
        p.Kp2[0] = QKV1h + 512; p.Vp2[0] = QKV1h + 1024; p.Op[0] = OUTC;
        p.Qp[1] = QKV1h; p.Kp[1] = QKV1h + 512; p.Vp[1] = QKV1h + 1024;
        p.Kp2[1] = QKV0h + 512; p.Vp2[1] = QKV0h + 1024; p.Op[1] = OUTC + 512;
        p.sq = 3 * HDIM; p.skv = 3 * HDIM; p.so = 2 * HDIM; p.cmask = 1; p.cshift = 1;
        flash_k<true><<<dim3(SEQL / 128, 8, BATCH * 2), blk, FSM_D>>>(p);
    }

    // 3) fully-fused out+cat+in_proj gemm: QKV2 = OUTC @ W2^T + BCOMB2
    {
        GemmP p = {};
        p.A1[0] = p.A1[1] = p.A1[2] = OUTC;
        p.W[0] = W2; p.W[1] = W2 + (size_t)512 * 1024; p.W[2] = W2 + (size_t)1024 * 1024;
        p.Bi[0] = BCOMB2; p.Bi[1] = BCOMB2 + 512; p.Bi[2] = BCOMB2 + 1024;
        p.Ch[0] = QKV2h; p.Ch[1] = QKV2h + 512; p.Ch[2] = QKV2h + 1024;
        p.osc[0] = qsc; p.osc[1] = 1.f; p.osc[2] = 1.f;
        p.lda = 2 * HDIM; p.ldc = 3 * HDIM; p.K = 1024; p.ldw = 1024;
        gemm_k<false><<<dim3(12, 64), blk, GSM>>>(p);
    }

    // 4) pooling self-attention (single-KV)
    {
        FlashP p;
        p.Qp[0] = QKV2h; p.Kp[0] = QKV2h + 512; p.Vp[0] = QKV2h + 1024;
        p.Kp2[0] = nullptr; p.Vp2[0] = nullptr; p.Op[0] = CTXh;
        p.sq = 3 * HDIM; p.skv = 3 * HDIM; p.so = HDIM; p.cmask = 0; p.cshift = 0;
        flash_k<false><<<dim3(SEQL / 128, 8, BATCH), blk, FSM_S>>>(p);
    }

    // 5) out_proj -> fp32 output
    {
        GemmP p = {};
        p.A1[0] = CTXh; p.W[0] = whop; p.Bi[0] = out_proj_b;
        p.Cf = out; p.osc[0] = 1.f;
        p.lda = HDIM; p.ldc = HDIM; p.K = HDIM; p.ldw = HDIM;
        gemm_k<true><<<dim3(4, 64), blk, GSM>>>(p);
    }
}

// round 14
// speedup vs baseline: 1.0691x; 1.0691x over previous
#include <cuda_runtime.h>
#include <cuda_fp16.h>
#include <math.h>
#include <stdint.h>

#define HDIM 512
#define BATCH 8
#define SEQL 1024
#define MTOT 8192

// half scratch: 84M halves = 168MB
__device__ __half g_scratch[(size_t)84 * 1024 * 1024];
__device__ float zbias[512] = {};   // zero bias for prep gemm

// ---------------------------------------------------------------------------
// Primitives
// ---------------------------------------------------------------------------
__device__ __forceinline__ void mma_f16(float& d0, float& d1, float& d2, float& d3,
                                        uint32_t a0, uint32_t a1, uint32_t a2, uint32_t a3,
                                        uint32_t b0, uint32_t b1)
{
    asm volatile(
        "mma.sync.aligned.m16n8k16.row.col.f32.f16.f16.f32 "
        "{%0,%1,%2,%3}, {%4,%5,%6,%7}, {%8,%9}, {%0,%1,%2,%3};"
        : "+f"(d0), "+f"(d1), "+f"(d2), "+f"(d3)
        : "r"(a0), "r"(a1), "r"(a2), "r"(a3), "r"(b0), "r"(b1));
}

__device__ __forceinline__ void ldsm4(uint32_t& r0, uint32_t& r1, uint32_t& r2, uint32_t& r3,
                                      uint32_t addr)
{
    asm volatile("ldmatrix.sync.aligned.m8n8.x4.shared.b16 {%0,%1,%2,%3}, [%4];"
                 : "=r"(r0), "=r"(r1), "=r"(r2), "=r"(r3) : "r"(addr));
}
__device__ __forceinline__ void ldsm4t(uint32_t& r0, uint32_t& r1, uint32_t& r2, uint32_t& r3,
                                       uint32_t addr)
{
    asm volatile("ldmatrix.sync.aligned.m8n8.x4.trans.shared.b16 {%0,%1,%2,%3}, [%4];"
                 : "=r"(r0), "=r"(r1), "=r"(r2), "=r"(r3) : "r"(addr));
}

__device__ __forceinline__ void cp16(uint32_t dst, const void* src) {
    asm volatile("cp.async.cg.shared.global [%0], [%1], 16;" :: "r"(dst), "l"(src));
}
__device__ __forceinline__ void cpcommit() { asm volatile("cp.async.commit_group;"); }
template<int N> __device__ __forceinline__ void cpwait() {
    asm volatile("cp.async.wait_group %0;" :: "n"(N));
}

// XOR swizzle: rows of 128B (64 halves), 16B chunk c in 0..7
__device__ __forceinline__ uint32_t swz(uint32_t r, uint32_t c) {
    return r * 128u + ((c ^ (r & 7u)) << 4);
}

__device__ __forceinline__ uint32_t packh2(float x, float y) {
    __half2 h = __floats2half2_rn(x, y);
    return *(uint32_t*)&h;
}

// ---------------------------------------------------------------------------
// fp32 -> fp16 conversion kernel
// ---------------------------------------------------------------------------
struct CvtP { const float* src[11]; __half* dst[11]; int nblk[11]; };

__global__ __launch_bounds__(256) void cvt_k(CvtP P)
{
    int b = blockIdx.x;
    int s = 0;
    while (b >= P.nblk[s]) { b -= P.nblk[s]; ++s; }
    size_t i = ((size_t)b * 256 + threadIdx.x) * 4;
    float4 v = *(const float4*)(P.src[s] + i);
    uint2 o;
    o.x = packh2(v.x, v.y);
    o.y = packh2(v.z, v.w);
    *(uint2*)(P.dst[s] + i) = o;
}

// ---------------------------------------------------------------------------
// transpose + cvt: dst[n,k] = fp16(src[k,n]) for 512x512 fp32 matrices
// ---------------------------------------------------------------------------
struct TrP { const float* src[2]; __half* dst[2]; };

__global__ void tcv_k(TrP P)
{
    __shared__ __half tile[32][33];
    const int s = blockIdx.z;
    const int x = blockIdx.x * 32, y = blockIdx.y * 32;
    const int tx = threadIdx.x, ty = threadIdx.y;
    const float* src = P.src[s];
    #pragma unroll
    for (int r = ty; r < 32; r += 8)
        tile[r][tx] = __float2half_rn(src[(size_t)(y + r) * 512 + x + tx]);
    __syncthreads();
    __half* dst = P.dst[s];
    #pragma unroll
    for (int r = ty; r < 32; r += 8)
        dst[(size_t)(x + r) * 512 + y + tx] = tile[tx][r];
}

// ---------------------------------------------------------------------------
// bias combine, warp-per-row (fp16 wcat):
//   bout[row] = bcat[row] + sum_j wcat[row,j]*([boi;bot])[j]
// block = 512 (16 warps), grid = 32
// ---------------------------------------------------------------------------
__global__ __launch_bounds__(512) void biascomb_k(
    const __half* __restrict__ wcat,
    const float* __restrict__ boi, const float* __restrict__ bot,
    const float* __restrict__ bcat, float* __restrict__ bout)
{
    const int row = blockIdx.x * 16 + (threadIdx.x >> 5);
    const int lane = threadIdx.x & 31;
    float s = 0.f;
    #pragma unroll 4
    for (int j = lane; j < 1024; j += 32) {
        const float b = (j < 512) ? boi[j] : bot[j - 512];
        s += __half2float(wcat[(size_t)row * 1024 + j]) * b;
    }
    #pragma unroll
    for (int o = 16; o; o >>= 1) s += __shfl_xor_sync(0xffffffffu, s, o);
    if (lane == 0) bout[row] = s + bcat[row];
}

// ---------------------------------------------------------------------------
// FP16 GEMM (NT): C = A @ W^T + bias, times per-seg osc. Pure cp.async A path.
// CTA tile 128x128, BK=64, 256 thr (8 warps 2x4, warp tile 64x32).
// 3-stage cp.async pipeline (96KB smem), single sync/iter, XOR swizzle.
// Up to 6 per-512-col segments.
// ---------------------------------------------------------------------------
struct GemmP {
    const __half* A1[6];
    const __half* W[6]; const float* Bi[6];
    __half* Ch[6]; float* Cf;
    float osc[6];
    int lda, ldc, K;
};

template<bool OUTF32>
__global__ __launch_bounds__(256, 2) void gemm_k(GemmP P)
{
    extern __shared__ char sm[];
    const uint32_t smb = (uint32_t)__cvta_generic_to_shared(sm);

    const int bm  = blockIdx.y * 128;
    const int bnG = blockIdx.x * 128;
    const int seg = bnG >> 9;
    const int bn  = bnG & 511;
    const __half* A1 = P.A1[seg];
    const __half* W  = P.W[seg];
    const float*  BI = P.Bi[seg];
    const float  osc = P.osc[seg];

    const int tid  = threadIdx.x;
    const int warp = tid >> 5;
    const int lane = tid & 31;
    const int g = lane >> 2;
    const int t = lane & 3;
    const int wm = warp >> 2;
    const int wn = warp & 3;
    const int lr = lane & 15;
    const int lh = lane >> 4;

    const int sr = tid >> 1;
    const int sc = (tid & 1) * 4;

    const uint32_t lrow128 = (uint32_t)lr * 128u;
    uint32_t x4[4];
    #pragma unroll
    for (int kb = 0; kb < 4; kb++)
        x4[kb] = (uint32_t)(((kb * 2 + lh) ^ (lr & 7)) << 4);

    const int NK = P.K >> 6;
    float acc[4][4][4] = {};

    auto stage = [&](int i) {
        const uint32_t da = smb + (uint32_t)(i % 3) * 32768u;
        const __half* sa = A1 + (size_t)(bm + sr) * P.lda + i * 64 + sc * 8;
        const __half* sw = W  + (size_t)(bn + sr) * P.K + i * 64 + sc * 8;
        #pragma unroll
        for (int c = 0; c < 4; c++) {
            cp16(da + swz(sr, sc + c), sa + c * 8);
            cp16(da + 16384u + swz(sr, sc + c), sw + c * 8);
        }
        cpcommit();
    };

    stage(0);
    if (NK > 1) stage(1);

    for (int i = 0; i < NK; i++) {
        if (i + 1 < NK) cpwait<1>(); else cpwait<0>();
        __syncthreads();

        const uint32_t Ab = smb + (uint32_t)(i % 3) * 32768u;
        const uint32_t Wb = Ab + 16384u;

        #pragma unroll
        for (int kb = 0; kb < 4; kb++) {
            uint32_t bw[2][4];
            #pragma unroll
            for (int np = 0; np < 2; np++)
                ldsm4(bw[np][0], bw[np][1], bw[np][2], bw[np][3],
                      Wb + (uint32_t)(wn * 32 + np * 16) * 128u + lrow128 + x4[kb]);
            #pragma unroll
            for (int mt = 0; mt < 4; mt++) {
                uint32_t a0, a1, a2, a3;
                ldsm4(a0, a1, a2, a3,
                      Ab + (uint32_t)(wm * 64 + mt * 16) * 128u + lrow128 + x4[kb]);
                #pragma unroll
                for (int nt = 0; nt < 4; nt++) {
                    const int np = nt >> 1, hi = nt & 1;
                    mma_f16(acc[mt][nt][0], acc[mt][nt][1], acc[mt][nt][2], acc[mt][nt][3],
                            a0, a1, a2, a3,
                            bw[np][hi ? 1 : 0], bw[np][hi ? 3 : 2]);
                }
            }
        }

        if (i + 2 < NK) stage(i + 2);
    }

    #pragma unroll
    for (int mt = 0; mt < 4; mt++) {
        const int r = bm + wm * 64 + mt * 16 + g;
        #pragma unroll
        for (int nt = 0; nt < 4; nt++) {
            const int cl = bn + wn * 32 + nt * 8 + 2 * t;
            const float bx = BI[cl], by = BI[cl + 1];
            if (OUTF32) {
                float* Cf = P.Cf;
                *(float2*)(Cf + (size_t)r * P.ldc + cl) =
                    make_float2((acc[mt][nt][0] + bx) * osc, (acc[mt][nt][1] + by) * osc);
                *(float2*)(Cf + (size_t)(r + 8) * P.ldc + cl) =
                    make_float2((acc[mt][nt][2] + bx) * osc, (acc[mt][nt][3] + by) * osc);
            } else {
                __half* Ch = P.Ch[seg];
                *(uint32_t*)(Ch + (size_t)r * P.ldc + cl) =
                    packh2((acc[mt][nt][0] + bx) * osc, (acc[mt][nt][1] + by) * osc);
                *(uint32_t*)(Ch + (size_t)(r + 8) * P.ldc + cl) =
                    packh2((acc[mt][nt][2] + bx) * osc, (acc[mt][nt][3] + by) * osc);
            }
        }
    }
}

// ---------------------------------------------------------------------------
// FP16 flash attention. DUAL: two KV streams against the same Q; the phase-A
// normalized output (x0.5) is stashed in smem (warp-private rows, no sync),
// phase B runs on KV2, epilogue writes 0.5*(Oa/la + Ob/lb).
// Inner loop identical to the R8 winner.
// ---------------------------------------------------------------------------
struct FlashP {
    const __half *Qp[4], *Kp[4], *Vp[4], *Kp2[4], *Vp2[4]; __half* Op[4];
    int sq, skv, so, cmask, cshift;
};

#define OS_STRIDE 68

template<bool DUAL>
__global__ __launch_bounds__(256, 2) void flash_k(FlashP P)
{
    extern __shared__ char fsm[];
    const uint32_t smb = (uint32_t)__cvta_generic_to_shared(fsm);

    const int z = blockIdx.z;
    const int c = z & P.cmask;
    const int b = z >> P.cshift;
    const int q0 = blockIdx.x * 128;
    const int h  = blockIdx.y;

    const int tid = threadIdx.x;
    const int w = tid >> 5;
    const int lane = tid & 31;
    const int g = lane >> 2;
    const int t = lane & 3;
    const int lr = lane & 15;
    const int lh = lane >> 4;

    const __half* Qb  = P.Qp[c] + (size_t)b * SEQL * P.sq  + (size_t)h * 64;
    const __half* Kb  = P.Kp[c] + (size_t)b * SEQL * P.skv + (size_t)h * 64;
    const __half* Vb  = P.Vp[c] + (size_t)b * SEQL * P.skv + (size_t)h * 64;
    const __half* Kb2 = DUAL ? P.Kp2[c] + (size_t)b * SEQL * P.skv + (size_t)h * 64 : nullptr;
    const __half* Vb2 = DUAL ? P.Vp2[c] + (size_t)b * SEQL * P.skv + (size_t)h * 64 : nullptr;
    __half*       Ob  = P.Op[c] + (size_t)b * SEQL * P.so  + (size_t)h * 64;

    const uint32_t lrow128 = (uint32_t)lr * 128u;
    uint32_t x4[4];
    #pragma unroll
    for (int kb = 0; kb < 4; kb++)
        x4[kb] = (uint32_t)(((kb * 2 + lh) ^ (lr & 7)) << 4);

    {
        const int sr = tid >> 1;
        const int sc = (tid & 1) * 4;
        const __half* src = Qb + (size_t)(q0 + sr) * P.sq + sc * 8;
        #pragma unroll
        for (int cc = 0; cc < 4; cc++)
            cp16(smb + swz(sr, sc + cc), src + cc * 8);
        cpcommit();
    }

    const int kr = tid >> 2;
    const int kc = (tid & 3) * 2;
    auto stageKV = [&](int tile) {
        const int s = tile % 3;
        const int kt = (DUAL ? (tile & 15) : tile) * 64;
        const __half* pk0 = (DUAL && (tile >> 4)) ? Kb2 : Kb;
        const __half* pv0 = (DUAL && (tile >> 4)) ? Vb2 : Vb;
        const __half* pk = pk0 + (size_t)(kt + kr) * P.skv + kc * 8;
        const __half* pv = pv0 + (size_t)(kt + kr) * P.skv + kc * 8;
        const uint32_t kbase = smb + 16384u + (uint32_t)s * 8192u;
        const uint32_t vbase = smb + 40960u + (uint32_t)s * 8192u;
        cp16(kbase + swz(kr, kc),     pk);
        cp16(kbase + swz(kr, kc + 1), pk + 8);
        cp16(vbase + swz(kr, kc),     pv);
        cp16(vbase + swz(kr, kc + 1), pv + 8);
        cpcommit();
    };

    stageKV(0);
    stageKV(1);
    cpwait<1>();
    __syncthreads();

    uint32_t qa[4][4];
    #pragma unroll
    for (int kb = 0; kb < 4; kb++)
        ldsm4(qa[kb][0], qa[kb][1], qa[kb][2], qa[kb][3],
              smb + (uint32_t)(w * 2048) + lrow128 + x4[kb]);

    float oacc[8][4] = {};
    float mi0 = -INFINITY, mi1 = -INFINITY;
    float li0 = 0.f, li1 = 0.f;

    const uint32_t ONES = 0x3C003C00u;
    float* Os = (float*)(fsm + 65536);
    const int rr = 16 * w + g;

    const int NT = DUAL ? 32 : 16;
    for (int it = 0; it < NT; it++) {
        const int s = it % 3;
        const uint32_t Kbase = smb + 16384u + (uint32_t)s * 8192u + lrow128;
        const uint32_t Vbase = smb + 40960u + (uint32_t)s * 8192u + lrow128;

        float sacc[8][4] = {};
        #pragma unroll
        for (int kb = 0; kb < 4; kb++) {
            #pragma unroll
            for (int np = 0; np < 4; np++) {
                uint32_t k0, k1, k2, k3;
                ldsm4(k0, k1, k2, k3, Kbase + (uint32_t)(np * 2048) + x4[kb]);
                mma_f16(sacc[2*np][0], sacc[2*np][1], sacc[2*np][2], sacc[2*np][3],
                        qa[kb][0], qa[kb][1], qa[kb][2], qa[kb][3], k0, k2);
                mma_f16(sacc[2*np+1][0], sacc[2*np+1][1], sacc[2*np+1][2], sacc[2*np+1][3],
                        qa[kb][0], qa[kb][1], qa[kb][2], qa[kb][3], k1, k3);
            }
        }

        uint32_t pa[4][4];
        {
            float mx0 = -INFINITY, mx1 = -INFINITY;
            #pragma unroll
            for (int nt = 0; nt < 8; nt++) {
                mx0 = fmaxf(mx0, fmaxf(sacc[nt][0], sacc[nt][1]));
                mx1 = fmaxf(mx1, fmaxf(sacc[nt][2], sacc[nt][3]));
            }
            mx0 = fmaxf(mx0, __shfl_xor_sync(0xffffffffu, mx0, 1, 4));
            mx0 = fmaxf(mx0, __shfl_xor_sync(0xffffffffu, mx0, 2, 4));
            mx1 = fmaxf(mx1, __shfl_xor_sync(0xffffffffu, mx1, 1, 4));
            mx1 = fmaxf(mx1, __shfl_xor_sync(0xffffffffu, mx1, 2, 4));
            const float mn0 = fmaxf(mi0, mx0);
            const float mn1 = fmaxf(mi1, mx1);
            const float c0 = exp2f(mi0 - mn0);
            const float c1 = exp2f(mi1 - mn1);
            mi0 = mn0; mi1 = mn1;

            float ls[4] = {0.f, 0.f, 0.f, 0.f};
            #pragma unroll
            for (int kb = 0; kb < 4; kb++) {
                __half2 e0 = h2exp2(__floats2half2_rn(sacc[2*kb][0]   - mn0, sacc[2*kb][1]   - mn0));
                __half2 e1 = h2exp2(__floats2half2_rn(sacc[2*kb][2]   - mn1, sacc[2*kb][3]   - mn1));
                __half2 e2 = h2exp2(__floats2half2_rn(sacc[2*kb+1][0] - mn0, sacc[2*kb+1][1] - mn0));
                __half2 e3 = h2exp2(__floats2half2_rn(sacc[2*kb+1][2] - mn1, sacc[2*kb+1][3] - mn1));
                pa[kb][0] = *(uint32_t*)&e0;
                pa[kb][1] = *(uint32_t*)&e1;
                pa[kb][2] = *(uint32_t*)&e2;
                pa[kb][3] = *(uint32_t*)&e3;
                mma_f16(ls[0], ls[1], ls[2], ls[3],
                        pa[kb][0], pa[kb][1], pa[kb][2], pa[kb][3], ONES, ONES);
            }
            li0 = li0 * c0 + ls[0];
            li1 = li1 * c1 + ls[2];

            const bool skip = __all_sync(0xffffffffu, (c0 == 1.0f) & (c1 == 1.0f));
            if (!skip) {
                #pragma unroll
                for (int nt = 0; nt < 8; nt++) {
                    oacc[nt][0] *= c0; oacc[nt][1] *= c0;
                    oacc[nt][2] *= c1; oacc[nt][3] *= c1;
                }
            }
        }

        #pragma unroll
        for (int kb = 0; kb < 4; kb++) {
            #pragma unroll
            for (int np = 0; np < 4; np++) {
                uint32_t v0, v1, v2, v3;
                ldsm4t(v0, v1, v2, v3, Vbase + (uint32_t)(kb * 2048) + x4[np]);
                mma_f16(oacc[2*np][0], oacc[2*np][1], oacc[2*np][2], oacc[2*np][3],
                        pa[kb][0], pa[kb][1], pa[kb][2], pa[kb][3], v0, v1);
                mma_f16(oacc[2*np+1][0], oacc[2*np+1][1], oacc[2*np+1][2], oacc[2*np+1][3],
                        pa[kb][0], pa[kb][1], pa[kb][2], pa[kb][3], v2, v3);
            }
        }

        // DUAL phase boundary: stash normalized phase-A output, reset stats
        if (DUAL && it == 15) {
            const float s0 = 0.5f / li0;
            const float s1 = 0.5f / li1;
            #pragma unroll
            for (int nt = 0; nt < 8; nt++) {
                const int col = nt * 8 + 2 * t;
                Os[rr * OS_STRIDE + col]           = oacc[nt][0] * s0;
                Os[rr * OS_STRIDE + col + 1]       = oacc[nt][1] * s0;
                Os[(rr + 8) * OS_STRIDE + col]     = oacc[nt][2] * s1;
                Os[(rr + 8) * OS_STRIDE + col + 1] = oacc[nt][3] * s1;
                oacc[nt][0] = oacc[nt][1] = oacc[nt][2] = oacc[nt][3] = 0.f;
            }
            mi0 = mi1 = -INFINITY;
            li0 = li1 = 0.f;
        }

        if (it + 1 < NT) {
            if (it + 2 < NT) { stageKV(it + 2); cpwait<1>(); }
            else             { cpwait<0>(); }
            __syncthreads();
        }
    }

    if (DUAL) {
        const float inv0 = 0.5f / li0;
        const float inv1 = 0.5f / li1;
        const int r0 = q0 + rr;
        #pragma unroll
        for (int nt = 0; nt < 8; nt++) {
            const int col = nt * 8 + 2 * t;
            float o00 = Os[rr * OS_STRIDE + col]           + oacc[nt][0] * inv0;
            float o01 = Os[rr * OS_STRIDE + col + 1]       + oacc[nt][1] * inv0;
            float o10 = Os[(rr + 8) * OS_STRIDE + col]     + oacc[nt][2] * inv1;
            float o11 = Os[(rr + 8) * OS_STRIDE + col + 1] + oacc[nt][3] * inv1;
            *(uint32_t*)(Ob + (size_t)r0 * P.so + col)       = packh2(o00, o01);
            *(uint32_t*)(Ob + (size_t)(r0 + 8) * P.so + col) = packh2(o10, o11);
        }
    } else {
        const float inv0 = 1.0f / li0;
        const float inv1 = 1.0f / li1;
        const int r0 = q0 + rr;
        #pragma unroll
        for (int nt = 0; nt < 8; nt++) {
            const int col = nt * 8 + 2 * t;
            *(uint32_t*)(Ob + (size_t)r0 * P.so + col) =
                packh2(oacc[nt][0] * inv0, oacc[nt][1] * inv0);
            *(uint32_t*)(Ob + (size_t)(r0 + 8) * P.so + col) =
                packh2(oacc[nt][2] * inv1, oacc[nt][3] * inv1);
        }
    }
}

// ---------------------------------------------------------------------------
extern "C" void kernel_launch(void* const* d_in, const int* in_sizes, int n_in,
                              void* d_out, int out_size)
{
    (void)in_sizes; (void)n_in; (void)out_size;

    const float* hs        = (const float*)d_in[0];
    const float* txt       = (const float*)d_in[1];
    const float* w_q_img   = (const float*)d_in[2];
    const float* b_q_img   = (const float*)d_in[3];
    const float* w_k_img   = (const float*)d_in[4];
    const float* b_k_img   = (const float*)d_in[5];
    const float* w_v_img   = (const float*)d_in[6];
    const float* b_v_img   = (const float*)d_in[7];
    const float* w_q_txt   = (const float*)d_in[8];
    const float* b_q_txt   = (const float*)d_in[9];
    const float* w_k_txt   = (const float*)d_in[10];
    const float* b_k_txt   = (const float*)d_in[11];
    const float* w_v_txt   = (const float*)d_in[12];
    const float* b_v_txt   = (const float*)d_in[13];
    const float* w_out_img = (const float*)d_in[14];
    const float* b_out_img = (const float*)d_in[15];
    const float* w_out_txt = (const float*)d_in[16];
    const float* b_out_txt = (const float*)d_in[17];
    const float* w_cat     = (const float*)d_in[18];
    const float* b_cat     = (const float*)d_in[19];
    const float* in_proj_w = (const float*)d_in[20];
    const float* in_proj_b = (const float*)d_in[21];
    const float* out_proj_w= (const float*)d_in[22];
    const float* out_proj_b= (const float*)d_in[23];
    float* out = (float*)d_out;

    constexpr size_t U  = (size_t)MTOT * HDIM;      // 4.19M halves
    constexpr size_t QW = (size_t)512 * 512;
    const float qsc = 0.125f * 1.4426950408889634f; // (1/sqrt(64))*log2(e)

    __half* S;
    cudaGetSymbolAddress((void**)&S, g_scratch);
    float* zb;
    cudaGetSymbolAddress((void**)&zb, zbias);

    __half* HSh    = S;
    __half* TXTh   = S + U;
    __half* QKV0h  = S + 2 * U;
    __half* QKV1h  = S + 5 * U;
    __half* OUTC   = S + 8 * U;               // [8192 x 1024] half
    __half* WCOMB  = S + 10 * U;              // [512 x 1024]
    __half* WOIT   = WCOMB + 512 * 1024;      // [512 x 512]
    __half* WOTT   = WOIT + QW;               // [512 x 512]
    float*  BCOMB  = (float*)(WOTT + QW);     // [512] fp32
    __half* OUTBh  = S + 11 * U;
    __half* QKV2h  = S + 12 * U;
    __half* CTXh   = S + 15 * U;
    __half* WB     = S + 16 * U;
    __half* whqi = WB;           __half* whki = WB + QW;     __half* whvi = WB + 2 * QW;
    __half* whqt = WB + 3 * QW;  __half* whkt = WB + 4 * QW; __half* whvt = WB + 5 * QW;
    __half* whop = WB + 6 * QW;
    __half* whcat = WB + 7 * QW;            // 512*1024
    __half* whinp = whcat + 512 * 1024;     // 1536*512

    const int GSM   = 98304;
    const int FSM_S = 65536;
    const int FSM_D = 65536 + 128 * OS_STRIDE * 4;   // +34816
    cudaFuncSetAttribute(gemm_k<false>,  cudaFuncAttributeMaxDynamicSharedMemorySize, GSM);
    cudaFuncSetAttribute(gemm_k<true>,   cudaFuncAttributeMaxDynamicSharedMemorySize, GSM);
    cudaFuncSetAttribute(flash_k<false>, cudaFuncAttributeMaxDynamicSharedMemorySize, FSM_S);
    cudaFuncSetAttribute(flash_k<true>,  cudaFuncAttributeMaxDynamicSharedMemorySize, FSM_D);

    // 0) fp32 -> fp16 conversions
    {
        CvtP p;
        const float* srcs[11] = {hs, txt, w_q_img, w_k_img, w_v_img, w_q_txt, w_k_txt,
                                 w_v_txt, out_proj_w, w_cat, in_proj_w};
        __half* dsts[11] = {HSh, TXTh, whqi, whki, whvi, whqt, whkt,
                            whvt, whop, whcat, whinp};
        int ns[11] = {(int)U, (int)U, (int)QW, (int)QW, (int)QW, (int)QW, (int)QW,
                      (int)QW, (int)QW, 512*1024, 1536*512};
        int tot = 0;
        for (int i = 0; i < 11; i++) { p.src[i]=srcs[i]; p.dst[i]=dsts[i]; p.nblk[i]=ns[i]/1024; tot+=ns[i]/1024; }
        cvt_k<<<tot, 256>>>(p);
    }

    // 0b) transpose+cvt w_out_img / w_out_txt
    {
        TrP p;
        p.src[0] = w_out_img; p.dst[0] = WOIT;
        p.src[1] = w_out_txt; p.dst[1] = WOTT;
        tcv_k<<<dim3(16, 16, 2), dim3(32, 8)>>>(p);
    }

    // 0c) prep gemm: WCOMB = [wcat_L @ w_oi | wcat_R @ w_ot]
    {
        GemmP p = {};
        p.A1[0] = whcat;  p.A1[1] = whcat + 512;
        p.W[0]  = WOIT;   p.W[1]  = WOTT;
        p.Bi[0] = zb;     p.Bi[1] = zb;
        p.Ch[0] = WCOMB;  p.Ch[1] = WCOMB + 512;
        p.osc[0] = p.osc[1] = 1.f;
        p.lda = 1024; p.ldc = 1024; p.K = 512;
        gemm_k<false><<<dim3(8, 4), dim3(256), GSM>>>(p);
    }

    // 0d) combined bias (warp-per-row)
    biascomb_k<<<32, 512>>>(whcat, b_out_img, b_out_txt, b_cat, BCOMB);

    const dim3 blk(256);

    // 1) BOTH QKV projections in one launch (6 half segments), Q pre-scaled
    {
        GemmP p = {};
        p.A1[0] = p.A1[1] = p.A1[2] = HSh;
        p.A1[3] = p.A1[4] = p.A1[5] = TXTh;
        p.W[0] = whqi; p.W[1] = whki; p.W[2] = whvi;
        p.W[3] = whqt; p.W[4] = whkt; p.W[5] = whvt;
        p.Bi[0] = b_q_img; p.Bi[1] = b_k_img; p.Bi[2] = b_v_img;
        p.Bi[3] = b_q_txt; p.Bi[4] = b_k_txt; p.Bi[5] = b_v_txt;
        p.Ch[0] = QKV0h; p.Ch[1] = QKV0h + 512; p.Ch[2] = QKV0h + 1024;
        p.Ch[3] = QKV1h; p.Ch[4] = QKV1h + 512; p.Ch[5] = QKV1h + 1024;
        p.osc[0] = qsc; p.osc[1] = 1.f; p.osc[2] = 1.f;
        p.osc[3] = qsc; p.osc[4] = 1.f; p.osc[5] = 1.f;
        p.lda = HDIM; p.ldc = 3 * HDIM; p.K = HDIM;
        gemm_k<false><<<dim3(24, 64), blk, GSM>>>(p);
    }

    // 2) dual-KV fused attentions: one CTA = both attentions for one Q stream
    {
        FlashP p;
        p.Qp[0] = QKV0h; p.Kp[0] = QKV0h + 512; p.Vp[0] = QKV0h + 1024;
        p.Kp2[0] = QKV1h + 512; p.Vp2[0] = QKV1h + 1024; p.Op[0] = OUTC;
        p.Qp[1] = QKV1h; p.Kp[1] = QKV1h + 512; p.Vp[1] = QKV1h + 1024;
        p.Kp2[1] = QKV0h + 512; p.Vp2[1] = QKV0h + 1024; p.Op[1] = OUTC + 512;
        p.sq = 3 * HDIM; p.skv = 3 * HDIM; p.so = 2 * HDIM; p.cmask = 1; p.cshift = 1;
        flash_k<true><<<dim3(SEQL / 128, 8, BATCH * 2), blk, FSM_D>>>(p);
    }

    // 3) combined out+cat gemm: OUTB = OUTC @ WCOMB^T + BCOMB (plain cp.async)
    {
        GemmP p = {};
        p.A1[0] = OUTC; p.W[0] = WCOMB; p.Bi[0] = BCOMB;
        p.Ch[0] = OUTBh; p.osc[0] = 1.f;
        p.lda = 2 * HDIM; p.ldc = HDIM; p.K = 1024;
        gemm_k<false><<<dim3(4, 64), blk, GSM>>>(p);
    }

    // 4) pooling in_proj, Q pre-scaled
    {
        GemmP p = {};
        p.A1[0] = p.A1[1] = p.A1[2] = OUTBh;
        p.W[0] = whinp; p.W[1] = whinp + 512 * 512; p.W[2] = whinp + 1024 * 512;
        p.Bi[0] = in_proj_b; p.Bi[1] = in_proj_b + 512; p.Bi[2] = in_proj_b + 1024;
        p.Ch[0] = QKV2h; p.Ch[1] = QKV2h + 512; p.Ch[2] = QKV2h + 1024;
        p.osc[0] = qsc; p.osc[1] = 1.f; p.osc[2] = 1.f;
        p.lda = HDIM; p.ldc = 3 * HDIM; p.K = HDIM;
        gemm_k<false><<<dim3(12, 64), blk, GSM>>>(p);
    }

    // 5) pooling self-attention (single-KV)
    {
        FlashP p;
        p.Qp[0] = QKV2h; p.Kp[0] = QKV2h + 512; p.Vp[0] = QKV2h + 1024;
        p.Kp2[0] = nullptr; p.Vp2[0] = nullptr; p.Op[0] = CTXh;
        p.sq = 3 * HDIM; p.skv = 3 * HDIM; p.so = HDIM; p.cmask = 0; p.cshift = 0;
        flash_k<false><<<dim3(SEQL / 128, 8, BATCH), blk, FSM_S>>>(p);
    }

    // 6) out_proj -> fp32 output
    {
        GemmP p = {};
        p.A1[0] = CTXh; p.W[0] = whop; p.Bi[0] = out_proj_b;
        p.Cf = out; p.osc[0] = 1.f;
        p.lda = HDIM; p.ldc = HDIM; p.K = HDIM;
        gemm_k<true><<<dim3(4, 64), blk, GSM>>>(p);
    }
}

// round 15
// speedup vs baseline: 1.1148x; 1.0427x over previous
#include <cuda_runtime.h>
#include <cuda_fp16.h>
#include <math.h>
#include <stdint.h>

#define HDIM 512
#define BATCH 8
#define SEQL 1024
#define MTOT 8192

// half scratch: 84M halves = 168MB
__device__ __half g_scratch[(size_t)84 * 1024 * 1024];
__device__ float zbias[512] = {};   // zero bias for prep gemm

// ---------------------------------------------------------------------------
// Primitives
// ---------------------------------------------------------------------------
__device__ __forceinline__ void mma_f16(float& d0, float& d1, float& d2, float& d3,
                                        uint32_t a0, uint32_t a1, uint32_t a2, uint32_t a3,
                                        uint32_t b0, uint32_t b1)
{
    asm volatile(
        "mma.sync.aligned.m16n8k16.row.col.f32.f16.f16.f32 "
        "{%0,%1,%2,%3}, {%4,%5,%6,%7}, {%8,%9}, {%0,%1,%2,%3};"
        : "+f"(d0), "+f"(d1), "+f"(d2), "+f"(d3)
        : "r"(a0), "r"(a1), "r"(a2), "r"(a3), "r"(b0), "r"(b1));
}

__device__ __forceinline__ void ldsm4(uint32_t& r0, uint32_t& r1, uint32_t& r2, uint32_t& r3,
                                      uint32_t addr)
{
    asm volatile("ldmatrix.sync.aligned.m8n8.x4.shared.b16 {%0,%1,%2,%3}, [%4];"
                 : "=r"(r0), "=r"(r1), "=r"(r2), "=r"(r3) : "r"(addr));
}
__device__ __forceinline__ void ldsm4t(uint32_t& r0, uint32_t& r1, uint32_t& r2, uint32_t& r3,
                                       uint32_t addr)
{
    asm volatile("ldmatrix.sync.aligned.m8n8.x4.trans.shared.b16 {%0,%1,%2,%3}, [%4];"
                 : "=r"(r0), "=r"(r1), "=r"(r2), "=r"(r3) : "r"(addr));
}

__device__ __forceinline__ void cp16(uint32_t dst, const void* src) {
    asm volatile("cp.async.cg.shared.global [%0], [%1], 16;" :: "r"(dst), "l"(src));
}
__device__ __forceinline__ void cpcommit() { asm volatile("cp.async.commit_group;"); }
template<int N> __device__ __forceinline__ void cpwait() {
    asm volatile("cp.async.wait_group %0;" :: "n"(N));
}

// XOR swizzle: rows of 128B (64 halves), 16B chunk c in 0..7
__device__ __forceinline__ uint32_t swz(uint32_t r, uint32_t c) {
    return r * 128u + ((c ^ (r & 7u)) << 4);
}

__device__ __forceinline__ uint32_t packh2(float x, float y) {
    __half2 h = __floats2half2_rn(x, y);
    return *(uint32_t*)&h;
}

// ---------------------------------------------------------------------------
// fp32 -> fp16 conversion kernel
// ---------------------------------------------------------------------------
struct CvtP { const float* src[8]; __half* dst[8]; int nblk[8]; };

__global__ __launch_bounds__(256) void cvt_k(CvtP P)
{
    int b = blockIdx.x;
    int s = 0;
    while (b >= P.nblk[s]) { b -= P.nblk[s]; ++s; }
    size_t i = ((size_t)b * 256 + threadIdx.x) * 4;
    float4 v = *(const float4*)(P.src[s] + i);
    uint2 o;
    o.x = packh2(v.x, v.y);
    o.y = packh2(v.z, v.w);
    *(uint2*)(P.dst[s] + i) = o;
}

// ---------------------------------------------------------------------------
// transpose + cvt: dst[n,k] = fp16(src[k,n]) for 512x512 fp32 matrices
// ---------------------------------------------------------------------------
struct TrP { const float* src[2]; __half* dst[2]; };

__global__ void tcv_k(TrP P)
{
    __shared__ __half tile[32][33];
    const int s = blockIdx.z;
    const int x = blockIdx.x * 32, y = blockIdx.y * 32;
    const int tx = threadIdx.x, ty = threadIdx.y;
    const float* src = P.src[s];
    #pragma unroll
    for (int r = ty; r < 32; r += 8)
        tile[r][tx] = __float2half_rn(src[(size_t)(y + r) * 512 + x + tx]);
    __syncthreads();
    __half* dst = P.dst[s];
    #pragma unroll
    for (int r = ty; r < 32; r += 8)
        dst[(size_t)(x + r) * 512 + y + tx] = tile[tx][r];
}

// ---------------------------------------------------------------------------
// bias combine (fp16 wcat): bout[n] = bcat[n] + sum_j wcat_h[n,j]*([boi;bot])[j]
// grid 512, block 256 (R12-proven config)
// ---------------------------------------------------------------------------
__global__ void biascomb_k(const __half* __restrict__ wcat,
                           const float* __restrict__ boi,
                           const float* __restrict__ bot,
                           const float* __restrict__ bcat,
                           float* __restrict__ bout)
{
    __shared__ float red[256];
    const int n = blockIdx.x;
    float s = 0.f;
    for (int j = threadIdx.x; j < 1024; j += 256) {
        const float b = (j < 512) ? boi[j] : bot[j - 512];
        s += __half2float(wcat[(size_t)n * 1024 + j]) * b;
    }
    red[threadIdx.x] = s;
    __syncthreads();
    #pragma unroll
    for (int o = 128; o; o >>= 1) {
        if (threadIdx.x < o) red[threadIdx.x] += red[threadIdx.x + o];
        __syncthreads();
    }
    if (threadIdx.x == 0) bout[n] = red[0] + bcat[n];
}

// ---------------------------------------------------------------------------
// FP16 GEMM (NT): C = A @ W^T + bias, times per-seg osc. Pure cp.async A path.
// CTA tile 128x128, BK=64, 256 thr (8 warps 2x4, warp tile 64x32).
// 3-stage cp.async pipeline (96KB smem), single sync/iter, XOR swizzle.
// Up to 6 per-512-col segments.
// ---------------------------------------------------------------------------
struct GemmP {
    const __half* A1[6];
    const __half* W[6]; const float* Bi[6];
    __half* Ch[6]; float* Cf;
    float osc[6];
    int lda, ldc, K;
};

template<bool OUTF32>
__global__ __launch_bounds__(256, 2) void gemm_k(GemmP P)
{
    extern __shared__ char sm[];
    const uint32_t smb = (uint32_t)__cvta_generic_to_shared(sm);

    const int bm  = blockIdx.y * 128;
    const int bnG = blockIdx.x * 128;
    const int seg = bnG >> 9;
    const int bn  = bnG & 511;
    const __half* A1 = P.A1[seg];
    const __half* W  = P.W[seg];
    const float*  BI = P.Bi[seg];
    const float  osc = P.osc[seg];

    const int tid  = threadIdx.x;
    const int warp = tid >> 5;
    const int lane = tid & 31;
    const int g = lane >> 2;
    const int t = lane & 3;
    const int wm = warp >> 2;
    const int wn = warp & 3;
    const int lr = lane & 15;
    const int lh = lane >> 4;

    const int sr = tid >> 1;
    const int sc = (tid & 1) * 4;

    const uint32_t lrow128 = (uint32_t)lr * 128u;
    uint32_t x4[4];
    #pragma unroll
    for (int kb = 0; kb < 4; kb++)
        x4[kb] = (uint32_t)(((kb * 2 + lh) ^ (lr & 7)) << 4);

    const int NK = P.K >> 6;
    float acc[4][4][4] = {};

    auto stage = [&](int i) {
        const uint32_t da = smb + (uint32_t)(i % 3) * 32768u;
        const __half* sa = A1 + (size_t)(bm + sr) * P.lda + i * 64 + sc * 8;
        const __half* sw = W  + (size_t)(bn + sr) * P.K + i * 64 + sc * 8;
        #pragma unroll
        for (int c = 0; c < 4; c++) {
            cp16(da + swz(sr, sc + c), sa + c * 8);
            cp16(da + 16384u + swz(sr, sc + c), sw + c * 8);
        }
        cpcommit();
    };

    stage(0);
    if (NK > 1) stage(1);

    for (int i = 0; i < NK; i++) {
        if (i + 1 < NK) cpwait<1>(); else cpwait<0>();
        __syncthreads();

        const uint32_t Ab = smb + (uint32_t)(i % 3) * 32768u;
        const uint32_t Wb = Ab + 16384u;

        #pragma unroll
        for (int kb = 0; kb < 4; kb++) {
            uint32_t bw[2][4];
            #pragma unroll
            for (int np = 0; np < 2; np++)
                ldsm4(bw[np][0], bw[np][1], bw[np][2], bw[np][3],
                      Wb + (uint32_t)(wn * 32 + np * 16) * 128u + lrow128 + x4[kb]);
            #pragma unroll
            for (int mt = 0; mt < 4; mt++) {
                uint32_t a0, a1, a2, a3;
                ldsm4(a0, a1, a2, a3,
                      Ab + (uint32_t)(wm * 64 + mt * 16) * 128u + lrow128 + x4[kb]);
                #pragma unroll
                for (int nt = 0; nt < 4; nt++) {
                    const int np = nt >> 1, hi = nt & 1;
                    mma_f16(acc[mt][nt][0], acc[mt][nt][1], acc[mt][nt][2], acc[mt][nt][3],
                            a0, a1, a2, a3,
                            bw[np][hi ? 1 : 0], bw[np][hi ? 3 : 2]);
                }
            }
        }

        if (i + 2 < NK) stage(i + 2);
    }

    #pragma unroll
    for (int mt = 0; mt < 4; mt++) {
        const int r = bm + wm * 64 + mt * 16 + g;
        #pragma unroll
        for (int nt = 0; nt < 4; nt++) {
            const int cl = bn + wn * 32 + nt * 8 + 2 * t;
            const float bx = BI[cl], by = BI[cl + 1];
            if (OUTF32) {
                float* Cf = P.Cf;
                *(float2*)(Cf + (size_t)r * P.ldc + cl) =
                    make_float2((acc[mt][nt][0] + bx) * osc, (acc[mt][nt][1] + by) * osc);
                *(float2*)(Cf + (size_t)(r + 8) * P.ldc + cl) =
                    make_float2((acc[mt][nt][2] + bx) * osc, (acc[mt][nt][3] + by) * osc);
            } else {
                __half* Ch = P.Ch[seg];
                *(uint32_t*)(Ch + (size_t)r * P.ldc + cl) =
                    packh2((acc[mt][nt][0] + bx) * osc, (acc[mt][nt][1] + by) * osc);
                *(uint32_t*)(Ch + (size_t)(r + 8) * P.ldc + cl) =
                    packh2((acc[mt][nt][2] + bx) * osc, (acc[mt][nt][3] + by) * osc);
            }
        }
    }
}

// ---------------------------------------------------------------------------
// FP16 flash attention. DUAL: two KV streams against the same Q; the phase-A
// normalized output (x0.5) is stashed in smem (warp-private rows, no sync),
// phase B runs on KV2, epilogue writes 0.5*(Oa/la + Ob/lb).
// ---------------------------------------------------------------------------
struct FlashP {
    const __half *Qp[4], *Kp[4], *Vp[4], *Kp2[4], *Vp2[4]; __half* Op[4];
    int sq, skv, so, cmask, cshift;
};

#define OS_STRIDE 68

template<bool DUAL>
__global__ __launch_bounds__(256, 2) void flash_k(FlashP P)
{
    extern __shared__ char fsm[];
    const uint32_t smb = (uint32_t)__cvta_generic_to_shared(fsm);

    const int z = blockIdx.z;
    const int c = z & P.cmask;
    const int b = z >> P.cshift;
    const int q0 = blockIdx.x * 128;
    const int h  = blockIdx.y;

    const int tid = threadIdx.x;
    const int w = tid >> 5;
    const int lane = tid & 31;
    const int g = lane >> 2;
    const int t = lane & 3;
    const int lr = lane & 15;
    const int lh = lane >> 4;

    const __half* Qb  = P.Qp[c] + (size_t)b * SEQL * P.sq  + (size_t)h * 64;
    const __half* Kb  = P.Kp[c] + (size_t)b * SEQL * P.skv + (size_t)h * 64;
    const __half* Vb  = P.Vp[c] + (size_t)b * SEQL * P.skv + (size_t)h * 64;
    const __half* Kb2 = DUAL ? P.Kp2[c] + (size_t)b * SEQL * P.skv + (size_t)h * 64 : nullptr;
    const __half* Vb2 = DUAL ? P.Vp2[c] + (size_t)b * SEQL * P.skv + (size_t)h * 64 : nullptr;
    __half*       Ob  = P.Op[c] + (size_t)b * SEQL * P.so  + (size_t)h * 64;

    const uint32_t lrow128 = (uint32_t)lr * 128u;
    uint32_t x4[4];
    #pragma unroll
    for (int kb = 0; kb < 4; kb++)
        x4[kb] = (uint32_t)(((kb * 2 + lh) ^ (lr & 7)) << 4);

    {
        const int sr = tid >> 1;
        const int sc = (tid & 1) * 4;
        const __half* src = Qb + (size_t)(q0 + sr) * P.sq + sc * 8;
        #pragma unroll
        for (int cc = 0; cc < 4; cc++)
            cp16(smb + swz(sr, sc + cc), src + cc * 8);
        cpcommit();
    }

    const int kr = tid >> 2;
    const int kc = (tid & 3) * 2;
    auto stageKV = [&](int tile) {
        const int s = tile % 3;
        const int kt = (DUAL ? (tile & 15) : tile) * 64;
        const __half* pk0 = (DUAL && (tile >> 4)) ? Kb2 : Kb;
        const __half* pv0 = (DUAL && (tile >> 4)) ? Vb2 : Vb;
        const __half* pk = pk0 + (size_t)(kt + kr) * P.skv + kc * 8;
        const __half* pv = pv0 + (size_t)(kt + kr) * P.skv + kc * 8;
        const uint32_t kbase = smb + 16384u + (uint32_t)s * 8192u;
        const uint32_t vbase = smb + 40960u + (uint32_t)s * 8192u;
        cp16(kbase + swz(kr, kc),     pk);
        cp16(kbase + swz(kr, kc + 1), pk + 8);
        cp16(vbase + swz(kr, kc),     pv);
        cp16(vbase + swz(kr, kc + 1), pv + 8);
        cpcommit();
    };

    stageKV(0);
    stageKV(1);
    cpwait<1>();
    __syncthreads();

    uint32_t qa[4][4];
    #pragma unroll
    for (int kb = 0; kb < 4; kb++)
        ldsm4(qa[kb][0], qa[kb][1], qa[kb][2], qa[kb][3],
              smb + (uint32_t)(w * 2048) + lrow128 + x4[kb]);

    float oacc[8][4] = {};
    float mi0 = -INFINITY, mi1 = -INFINITY;
    float li0 = 0.f, li1 = 0.f;

    const uint32_t ONES = 0x3C003C00u;
    float* Os = (float*)(fsm + 65536);
    const int rr = 16 * w + g;

    const int NT = DUAL ? 32 : 16;
    for (int it = 0; it < NT; it++) {
        const int s = it % 3;
        const uint32_t Kbase = smb + 16384u + (uint32_t)s * 8192u + lrow128;
        const uint32_t Vbase = smb + 40960u + (uint32_t)s * 8192u + lrow128;

        float sacc[8][4] = {};
        #pragma unroll
        for (int kb = 0; kb < 4; kb++) {
            #pragma unroll
            for (int np = 0; np < 4; np++) {
                uint32_t k0, k1, k2, k3;
                ldsm4(k0, k1, k2, k3, Kbase + (uint32_t)(np * 2048) + x4[kb]);
                mma_f16(sacc[2*np][0], sacc[2*np][1], sacc[2*np][2], sacc[2*np][3],
                        qa[kb][0], qa[kb][1], qa[kb][2], qa[kb][3], k0, k2);
                mma_f16(sacc[2*np+1][0], sacc[2*np+1][1], sacc[2*np+1][2], sacc[2*np+1][3],
                        qa[kb][0], qa[kb][1], qa[kb][2], qa[kb][3], k1, k3);
            }
        }

        uint32_t pa[4][4];
        {
            float mx0 = -INFINITY, mx1 = -INFINITY;
            #pragma unroll
            for (int nt = 0; nt < 8; nt++) {
                mx0 = fmaxf(mx0, fmaxf(sacc[nt][0], sacc[nt][1]));
                mx1 = fmaxf(mx1, fmaxf(sacc[nt][2], sacc[nt][3]));
            }
            mx0 = fmaxf(mx0, __shfl_xor_sync(0xffffffffu, mx0, 1, 4));
            mx0 = fmaxf(mx0, __shfl_xor_sync(0xffffffffu, mx0, 2, 4));
            mx1 = fmaxf(mx1, __shfl_xor_sync(0xffffffffu, mx1, 1, 4));
            mx1 = fmaxf(mx1, __shfl_xor_sync(0xffffffffu, mx1, 2, 4));
            const float mn0 = fmaxf(mi0, mx0);
            const float mn1 = fmaxf(mi1, mx1);
            const float c0 = exp2f(mi0 - mn0);
            const float c1 = exp2f(mi1 - mn1);
            mi0 = mn0; mi1 = mn1;

            float ls[4] = {0.f, 0.f, 0.f, 0.f};
            #pragma unroll
            for (int kb = 0; kb < 4; kb++) {
                __half2 e0 = h2exp2(__floats2half2_rn(sacc[2*kb][0]   - mn0, sacc[2*kb][1]   - mn0));
                __half2 e1 = h2exp2(__floats2half2_rn(sacc[2*kb][2]   - mn1, sacc[2*kb][3]   - mn1));
                __half2 e2 = h2exp2(__floats2half2_rn(sacc[2*kb+1][0] - mn0, sacc[2*kb+1][1] - mn0));
                __half2 e3 = h2exp2(__floats2half2_rn(sacc[2*kb+1][2] - mn1, sacc[2*kb+1][3] - mn1));
                pa[kb][0] = *(uint32_t*)&e0;
                pa[kb][1] = *(uint32_t*)&e1;
                pa[kb][2] = *(uint32_t*)&e2;
                pa[kb][3] = *(uint32_t*)&e3;
                mma_f16(ls[0], ls[1], ls[2], ls[3],
                        pa[kb][0], pa[kb][1], pa[kb][2], pa[kb][3], ONES, ONES);
            }
            li0 = li0 * c0 + ls[0];
            li1 = li1 * c1 + ls[2];

            const bool skip = __all_sync(0xffffffffu, (c0 == 1.0f) & (c1 == 1.0f));
            if (!skip) {
                #pragma unroll
                for (int nt = 0; nt < 8; nt++) {
                    oacc[nt][0] *= c0; oacc[nt][1] *= c0;
                    oacc[nt][2] *= c1; oacc[nt][3] *= c1;
                }
            }
        }

        #pragma unroll
        for (int kb = 0; kb < 4; kb++) {
            #pragma unroll
            for (int np = 0; np < 4; np++) {
                uint32_t v0, v1, v2, v3;
                ldsm4t(v0, v1, v2, v3, Vbase + (uint32_t)(kb * 2048) + x4[np]);
                mma_f16(oacc[2*np][0], oacc[2*np][1], oacc[2*np][2], oacc[2*np][3],
                        pa[kb][0], pa[kb][1], pa[kb][2], pa[kb][3], v0, v1);
                mma_f16(oacc[2*np+1][0], oacc[2*np+1][1], oacc[2*np+1][2], oacc[2*np+1][3],
                        pa[kb][0], pa[kb][1], pa[kb][2], pa[kb][3], v2, v3);
            }
        }

        // DUAL phase boundary: stash normalized phase-A output, reset stats
        if (DUAL && it == 15) {
            const float s0 = 0.5f / li0;
            const float s1 = 0.5f / li1;
            #pragma unroll
            for (int nt = 0; nt < 8; nt++) {
                const int col = nt * 8 + 2 * t;
                Os[rr * OS_STRIDE + col]           = oacc[nt][0] * s0;
                Os[rr * OS_STRIDE + col + 1]       = oacc[nt][1] * s0;
                Os[(rr + 8) * OS_STRIDE + col]     = oacc[nt][2] * s1;
                Os[(rr + 8) * OS_STRIDE + col + 1] = oacc[nt][3] * s1;
                oacc[nt][0] = oacc[nt][1] = oacc[nt][2] = oacc[nt][3] = 0.f;
            }
            mi0 = mi1 = -INFINITY;
            li0 = li1 = 0.f;
        }

        if (it + 1 < NT) {
            if (it + 2 < NT) { stageKV(it + 2); cpwait<1>(); }
            else             { cpwait<0>(); }
            __syncthreads();
        }
    }

    if (DUAL) {
        const float inv0 = 0.5f / li0;
        const float inv1 = 0.5f / li1;
        const int r0 = q0 + rr;
        #pragma unroll
        for (int nt = 0; nt < 8; nt++) {
            const int col = nt * 8 + 2 * t;
            float o00 = Os[rr * OS_STRIDE + col]           + oacc[nt][0] * inv0;
            float o01 = Os[rr * OS_STRIDE + col + 1]       + oacc[nt][1] * inv0;
            float o10 = Os[(rr + 8) * OS_STRIDE + col]     + oacc[nt][2] * inv1;
            float o11 = Os[(rr + 8) * OS_STRIDE + col + 1] + oacc[nt][3] * inv1;
            *(uint32_t*)(Ob + (size_t)r0 * P.so + col)       = packh2(o00, o01);
            *(uint32_t*)(Ob + (size_t)(r0 + 8) * P.so + col) = packh2(o10, o11);
        }
    } else {
        const float inv0 = 1.0f / li0;
        const float inv1 = 1.0f / li1;
        const int r0 = q0 + rr;
        #pragma unroll
        for (int nt = 0; nt < 8; nt++) {
            const int col = nt * 8 + 2 * t;
            *(uint32_t*)(Ob + (size_t)r0 * P.so + col) =
                packh2(oacc[nt][0] * inv0, oacc[nt][1] * inv0);
            *(uint32_t*)(Ob + (size_t)(r0 + 8) * P.so + col) =
                packh2(oacc[nt][2] * inv1, oacc[nt][3] * inv1);
        }
    }
}

// ---------------------------------------------------------------------------
extern "C" void kernel_launch(void* const* d_in, const int* in_sizes, int n_in,
                              void* d_out, int out_size)
{
    (void)in_sizes; (void)n_in; (void)out_size;

    const float* hs        = (const float*)d_in[0];
    const float* txt       = (const float*)d_in[1];
    const float* w_q_img   = (const float*)d_in[2];
    const float* b_q_img   = (const float*)d_in[3];
    const float* w_k_img   = (const float*)d_in[4];
    const float* b_k_img   = (const float*)d_in[5];
    const float* w_v_img   = (const float*)d_in[6];
    const float* b_v_img   = (const float*)d_in[7];
    const float* w_q_txt   = (const float*)d_in[8];
    const float* b_q_txt   = (const float*)d_in[9];
    const float* w_k_txt   = (const float*)d_in[10];
    const float* b_k_txt   = (const float*)d_in[11];
    const float* w_v_txt   = (const float*)d_in[12];
    const float* b_v_txt   = (const float*)d_in[13];
    const float* w_out_img = (const float*)d_in[14];
    const float* b_out_img = (const float*)d_in[15];
    const float* w_out_txt = (const float*)d_in[16];
    const float* b_out_txt = (const float*)d_in[17];
    const float* w_cat     = (const float*)d_in[18];
    const float* b_cat     = (const float*)d_in[19];
    const float* in_proj_w = (const float*)d_in[20];
    const float* in_proj_b = (const float*)d_in[21];
    const float* out_proj_w= (const float*)d_in[22];
    const float* out_proj_b= (const float*)d_in[23];
    float* out = (float*)d_out;

    constexpr size_t U  = (size_t)MTOT * HDIM;      // 4.19M halves
    constexpr size_t QW = (size_t)512 * 512;
    const float qsc = 0.125f * 1.4426950408889634f; // (1/sqrt(64))*log2(e)

    __half* S;
    cudaGetSymbolAddress((void**)&S, g_scratch);
    float* zb;
    cudaGetSymbolAddress((void**)&zb, zbias);

    __half* HSh    = S;
    __half* TXTh   = S + U;
    __half* QKV0h  = S + 2 * U;
    __half* QKV1h  = S + 5 * U;
    __half* OUTC   = S + 8 * U;               // [8192 x 1024] half
    __half* WCOMB  = S + 10 * U;              // [512 x 1024]
    __half* WOIT   = WCOMB + 512 * 1024;      // [512 x 512]
    __half* WOTT   = WOIT + QW;               // [512 x 512]
    float*  BCOMB  = (float*)(WOTT + QW);     // [512] fp32
    __half* OUTBh  = S + 11 * U;
    __half* QKV2h  = S + 12 * U;
    __half* CTXh   = S + 15 * U;
    __half* WB     = S + 16 * U;
    __half* whqi = WB;           __half* whki = WB + QW;     __half* whvi = WB + 2 * QW;
    __half* whqt = WB + 3 * QW;  __half* whkt = WB + 4 * QW; __half* whvt = WB + 5 * QW;
    __half* whop = WB + 6 * QW;
    __half* whcat = WB + 7 * QW;            // 512*1024
    __half* whinp = whcat + 512 * 1024;     // 1536*512

    const int GSM   = 98304;
    const int FSM_S = 65536;
    const int FSM_D = 65536 + 128 * OS_STRIDE * 4;   // +34816
    cudaFuncSetAttribute(gemm_k<false>,  cudaFuncAttributeMaxDynamicSharedMemorySize, GSM);
    cudaFuncSetAttribute(gemm_k<true>,   cudaFuncAttributeMaxDynamicSharedMemorySize, GSM);
    cudaFuncSetAttribute(flash_k<false>, cudaFuncAttributeMaxDynamicSharedMemorySize, FSM_S);
    cudaFuncSetAttribute(flash_k<true>,  cudaFuncAttributeMaxDynamicSharedMemorySize, FSM_D);

    // fork machinery (host-side objects only; capture-legal)
    cudaStream_t side;
    cudaStreamCreateWithFlags(&side, cudaStreamNonBlocking);
    cudaEvent_t e0, e1;
    cudaEventCreateWithFlags(&e0, cudaEventDisableTiming);
    cudaEventCreateWithFlags(&e1, cudaEventDisableTiming);

    // 0) MAIN: convert inputs + QKV weights (everything the main path needs first)
    {
        CvtP p;
        const float* srcs[8] = {hs, txt, w_q_img, w_k_img, w_v_img, w_q_txt, w_k_txt, w_v_txt};
        __half* dsts[8] = {HSh, TXTh, whqi, whki, whvi, whqt, whkt, whvt};
        int ns[8] = {(int)U, (int)U, (int)QW, (int)QW, (int)QW, (int)QW, (int)QW, (int)QW};
        int tot = 0;
        for (int i = 0; i < 8; i++) { p.src[i]=srcs[i]; p.dst[i]=dsts[i]; p.nblk[i]=ns[i]/1024; tot+=ns[i]/1024; }
        cvt_k<<<tot, 256>>>(p);
    }
    cudaEventRecord(e0, 0);

    // SIDE branch: remaining weight cvt + WCOMB/BCOMB prep (overlaps QKV+flash)
    cudaStreamWaitEvent(side, e0, 0);
    {
        CvtP p = {};
        const float* srcs[3] = {out_proj_w, w_cat, in_proj_w};
        __half* dsts[3] = {whop, whcat, whinp};
        int ns[3] = {(int)QW, 512*1024, 1536*512};
        int tot = 0;
        for (int i = 0; i < 3; i++) { p.src[i]=srcs[i]; p.dst[i]=dsts[i]; p.nblk[i]=ns[i]/1024; tot+=ns[i]/1024; }
        for (int i = 3; i < 8; i++) { p.src[i]=srcs[0]; p.dst[i]=dsts[0]; p.nblk[i]=0; }
        cvt_k<<<tot, 256, 0, side>>>(p);
    }
    {
        TrP p;
        p.src[0] = w_out_img; p.dst[0] = WOIT;
        p.src[1] = w_out_txt; p.dst[1] = WOTT;
        tcv_k<<<dim3(16, 16, 2), dim3(32, 8), 0, side>>>(p);
    }
    {
        GemmP p = {};
        p.A1[0] = whcat;  p.A1[1] = whcat + 512;
        p.W[0]  = WOIT;   p.W[1]  = WOTT;
        p.Bi[0] = zb;     p.Bi[1] = zb;
        p.Ch[0] = WCOMB;  p.Ch[1] = WCOMB + 512;
        p.osc[0] = p.osc[1] = 1.f;
        p.lda = 1024; p.ldc = 1024; p.K = 512;
        gemm_k<false><<<dim3(8, 4), dim3(256), GSM, side>>>(p);
    }
    biascomb_k<<<512, 256, 0, side>>>(whcat, b_out_img, b_out_txt, b_cat, BCOMB);
    cudaEventRecord(e1, side);

    const dim3 blk(256);

    // 1) MAIN: both QKV projections in one launch (6 half segments), Q pre-scaled
    {
        GemmP p = {};
        p.A1[0] = p.A1[1] = p.A1[2] = HSh;
        p.A1[3] = p.A1[4] = p.A1[5] = TXTh;
        p.W[0] = whqi; p.W[1] = whki; p.W[2] = whvi;
        p.W[3] = whqt; p.W[4] = whkt; p.W[5] = whvt;
        p.Bi[0] = b_q_img; p.Bi[1] = b_k_img; p.Bi[2] = b_v_img;
        p.Bi[3] = b_q_txt; p.Bi[4] = b_k_txt; p.Bi[5] = b_v_txt;
        p.Ch[0] = QKV0h; p.Ch[1] = QKV0h + 512; p.Ch[2] = QKV0h + 1024;
        p.Ch[3] = QKV1h; p.Ch[4] = QKV1h + 512; p.Ch[5] = QKV1h + 1024;
        p.osc[0] = qsc; p.osc[1] = 1.f; p.osc[2] = 1.f;
        p.osc[3] = qsc; p.osc[4] = 1.f; p.osc[5] = 1.f;
        p.lda = HDIM; p.ldc = 3 * HDIM; p.K = HDIM;
        gemm_k<false><<<dim3(24, 64), blk, GSM>>>(p);
    }

    // 2) MAIN: dual-KV fused attentions
    {
        FlashP p;
        p.Qp[0] = QKV0h; p.Kp[0] = QKV0h + 512; p.Vp[0] = QKV0h + 1024;
        p.Kp2[0] = QKV1h + 512; p.Vp2[0] = QKV1h + 1024; p.Op[0] = OUTC;
        p.Qp[1] = QKV1h; p.Kp[1] = QKV1h + 512; p.Vp[1] = QKV1h + 1024;
        p.Kp2[1] = QKV0h + 512; p.Vp2[1] = QKV0h + 1024; p.Op[1] = OUTC + 512;
        p.sq = 3 * HDIM; p.skv = 3 * HDIM; p.so = 2 * HDIM; p.cmask = 1; p.cshift = 1;
        flash_k<true><<<dim3(SEQL / 128, 8, BATCH * 2), blk, FSM_D>>>(p);
    }

    // join: prep results needed from here on
    cudaStreamWaitEvent(0, e1, 0);

    // 3) combined out+cat gemm: OUTB = OUTC @ WCOMB^T + BCOMB
    {
        GemmP p = {};
        p.A1[0] = OUTC; p.W[0] = WCOMB; p.Bi[0] = BCOMB;
        p.Ch[0] = OUTBh; p.osc[0] = 1.f;
        p.lda = 2 * HDIM; p.ldc = HDIM; p.K = 1024;
        gemm_k<false><<<dim3(4, 64), blk, GSM>>>(p);
    }

    // 4) pooling in_proj, Q pre-scaled
    {
        GemmP p = {};
        p.A1[0] = p.A1[1] = p.A1[2] = OUTBh;
        p.W[0] = whinp; p.W[1] = whinp + 512 * 512; p.W[2] = whinp + 1024 * 512;
        p.Bi[0] = in_proj_b; p.Bi[1] = in_proj_b + 512; p.Bi[2] = in_proj_b + 1024;
        p.Ch[0] = QKV2h; p.Ch[1] = QKV2h + 512; p.Ch[2] = QKV2h + 1024;
        p.osc[0] = qsc; p.osc[1] = 1.f; p.osc[2] = 1.f;
        p.lda = HDIM; p.ldc = 3 * HDIM; p.K = HDIM;
        gemm_k<false><<<dim3(12, 64), blk, GSM>>>(p);
    }

    // 5) pooling self-attention (single-KV)
    {
        FlashP p;
        p.Qp[0] = QKV2h; p.Kp[0] = QKV2h + 512; p.Vp[0] = QKV2h + 1024;
        p.Kp2[0] = nullptr; p.Vp2[0] = nullptr; p.Op[0] = CTXh;
        p.sq = 3 * HDIM; p.skv = 3 * HDIM; p.so = HDIM; p.cmask = 0; p.cshift = 0;
        flash_k<false><<<dim3(SEQL / 128, 8, BATCH), blk, FSM_S>>>(p);
    }

    // 6) out_proj -> fp32 output
    {
        GemmP p = {};
        p.A1[0] = CTXh; p.W[0] = whop; p.Bi[0] = out_proj_b;
        p.Cf = out; p.osc[0] = 1.f;
        p.lda = HDIM; p.ldc = HDIM; p.K = HDIM;
        gemm_k<true><<<dim3(4, 64), blk, GSM>>>(p);
    }

    cudaEventDestroy(e0);
    cudaEventDestroy(e1);
    cudaStreamDestroy(side);
}